// round 12
// baseline (speedup 1.0000x reference)
#include <cuda_runtime.h>
#include <cuda_bf16.h>
#include <cstdint>

#define NN 100000
#define EE 1600000
#define FEAT 128
#define SCAN_BLK 1024

// ---------------- device scratch ----------------
__device__ float g_agg[NN * FEAT];
__device__ float g_z[NN * 2];
__device__ float g_s[NN * 2];
__device__ float g_A[2 * FEAT];
__device__ float g_B[2 * FEAT];
__device__ float g_c[2];
__device__ int g_count[NN];      // zero at load; re-zeroed by gather2 tail each run
__device__ int g_rowptr[NN + 1];
__device__ int g_cursor[NN];
__device__ int g_bsum[128];
__device__ int g_srcs[EE];

// ---------------- helpers ----------------
__device__ __forceinline__ uint32_t smem_u32(const void* p) {
    uint32_t a;
    asm("{ .reg .u64 t; cvta.to.shared.u64 t, %1; cvt.u32.u64 %0, t; }" : "=r"(a) : "l"(p));
    return a;
}
__device__ __forceinline__ void ldsm_x4(uint32_t& r0, uint32_t& r1, uint32_t& r2, uint32_t& r3,
                                        uint32_t addr) {
    asm volatile("ldmatrix.sync.aligned.m8n8.x4.shared.b16 {%0,%1,%2,%3}, [%4];"
                 : "=r"(r0), "=r"(r1), "=r"(r2), "=r"(r3) : "r"(addr));
}
__device__ __forceinline__ void mma16816(float* c, const uint32_t* a, const uint32_t* b) {
    asm volatile(
        "mma.sync.aligned.m16n8k16.row.col.f32.bf16.bf16.f32 "
        "{%0,%1,%2,%3}, {%4,%5,%6,%7}, {%8,%9}, {%0,%1,%2,%3};"
        : "+f"(c[0]), "+f"(c[1]), "+f"(c[2]), "+f"(c[3])
        : "r"(a[0]), "r"(a[1]), "r"(a[2]), "r"(a[3]), "r"(b[0]), "r"(b[1]));
}
__device__ __forceinline__ uint2 pack_hi(float4 v) {
    __nv_bfloat162 p01 = __floats2bfloat162_rn(v.x, v.y);
    __nv_bfloat162 p23 = __floats2bfloat162_rn(v.z, v.w);
    return make_uint2(*(uint32_t*)&p01, *(uint32_t*)&p23);
}
__device__ __forceinline__ uint2 pack_lo(float4 v) {
    __nv_bfloat162 p01 = __floats2bfloat162_rn(v.x, v.y);
    __nv_bfloat162 p23 = __floats2bfloat162_rn(v.z, v.w);
    float4 lo;
    lo.x = v.x - __bfloat162float(__low2bfloat16(p01));
    lo.y = v.y - __bfloat162float(__high2bfloat16(p01));
    lo.z = v.z - __bfloat162float(__low2bfloat16(p23));
    lo.w = v.w - __bfloat162float(__high2bfloat16(p23));
    __nv_bfloat162 q01 = __floats2bfloat162_rn(lo.x, lo.y);
    __nv_bfloat162 q23 = __floats2bfloat162_rn(lo.z, lo.w);
    return make_uint2(*(uint32_t*)&q01, *(uint32_t*)&q23);
}
// local dtype probe: positive int64 values have zero odd int32 words
__device__ __forceinline__ int probe_is64(const void* ei) {
    const int* p = (const int*)ei;
    int orr = 0;
    #pragma unroll
    for (int j = 1; j < 32; j += 2) orr |= p[j];
    return (orr == 0) ? 1 : 0;
}
__device__ __forceinline__ int edge_at(const void* ei, int is64, long long idx) {
    if (is64) return (int)((const long long*)ei)[idx];
    return ((const int*)ei)[idx];
}

// ---------------- count (8 edges/thread) + weight folding in block 0 ----------------
__global__ void count_kernel(const void* __restrict__ ei, int E,
                             const float* __restrict__ W2l, const float* __restrict__ b2,
                             const float* __restrict__ W2r, const float* __restrict__ Wlin,
                             const float* __restrict__ blin) {
    if (blockIdx.x == 0) {
        int t = threadIdx.x;
        if (t < 256) {
            int o = t >> 7, f = t & 127;
            float a = 0.f, b = 0.f;
            #pragma unroll
            for (int k = 0; k < 4; k++) {
                float w = Wlin[o * 4 + k];
                a += w * W2l[k * FEAT + f];
                b += w * W2r[k * FEAT + f];
            }
            g_A[o * FEAT + f] = a;
            g_B[o * FEAT + f] = b;
        }
        if (t < 2) {
            float c = blin[t];
            #pragma unroll
            for (int k = 0; k < 4; k++) c += Wlin[t * 4 + k] * b2[k];
            g_c[t] = c;
        }
    }
    int is64 = probe_is64(ei);
    int e0 = blockIdx.x * (blockDim.x * 8) + threadIdx.x;
    int d[8];
    #pragma unroll
    for (int u = 0; u < 8; u++) {
        int e = e0 + u * blockDim.x;
        d[u] = (e < E) ? edge_at(ei, is64, (long long)E + e) : -1;
    }
    #pragma unroll
    for (int u = 0; u < 8; u++)
        if (d[u] >= 0) atomicAdd(&g_count[d[u]], 1);
}

// ---------------- scans ----------------
__global__ void scanA_kernel(int n) {
    __shared__ int s[SCAN_BLK];
    int t = threadIdx.x;
    int idx = blockIdx.x * SCAN_BLK + t;
    int v = (idx < n) ? g_count[idx] : 0;
    s[t] = v;
    __syncthreads();
    for (int off = 1; off < SCAN_BLK; off <<= 1) {
        int u = (t >= off) ? s[t - off] : 0;
        __syncthreads();
        s[t] += u;
        __syncthreads();
    }
    if (idx <= n) g_rowptr[idx] = s[t] - v;
    if (t == SCAN_BLK - 1) g_bsum[blockIdx.x] = s[t];
}
__global__ void scanC_kernel(int n, int E) {
    __shared__ int sb[128];
    int t = threadIdx.x;
    int bid = blockIdx.x;
    if (t < 128) sb[t] = (t < bid) ? g_bsum[t] : 0;
    __syncthreads();
    #pragma unroll
    for (int off = 64; off > 0; off >>= 1) {
        if (t < off) sb[t] += sb[t + off];
        __syncthreads();
    }
    int boff = sb[0];
    int idx = bid * SCAN_BLK + t;
    if (idx < n) {
        int r = g_rowptr[idx] + boff;
        g_rowptr[idx] = r;
        g_cursor[idx] = r;
    }
    if (idx == 0) g_rowptr[n] = E;
}

// ---------------- fill (8 edges/thread) ----------------
__global__ void fill_kernel(const void* __restrict__ ei, int E) {
    int is64 = probe_is64(ei);
    int e0 = blockIdx.x * (blockDim.x * 8) + threadIdx.x;
    int s[8], d[8];
    #pragma unroll
    for (int u = 0; u < 8; u++) {
        int e = e0 + u * blockDim.x;
        if (e < E) {
            s[u] = edge_at(ei, is64, e);
            d[u] = edge_at(ei, is64, (long long)E + e);
        } else d[u] = -1;
    }
    #pragma unroll
    for (int u = 0; u < 8; u++)
        if (d[u] >= 0) {
            int slot = atomicAdd(&g_cursor[d[u]], 1);
            g_srcs[slot] = s[u];
        }
}

// ---------------- gather1 (warp per node) ----------------
__global__ void gather1_kernel(const float* __restrict__ x, int n_nodes) {
    int w = (blockIdx.x * blockDim.x + threadIdx.x) >> 5;
    int lane = threadIdx.x & 31;
    if (w >= n_nodes) return;
    int beg = g_rowptr[w];
    int end = g_rowptr[w + 1];
    float4 acc = make_float4(0.f, 0.f, 0.f, 0.f);
    const float4* X = reinterpret_cast<const float4*>(x);
    for (int j0 = beg; j0 < end; j0 += 32) {
        int myid = (j0 + lane < end) ? g_srcs[j0 + lane] : 0;
        int cnt = min(32, end - j0);
        int k = 0;
        for (; k + 4 <= cnt; k += 4) {
            int s0 = __shfl_sync(0xffffffffu, myid, k);
            int s1 = __shfl_sync(0xffffffffu, myid, k + 1);
            int s2 = __shfl_sync(0xffffffffu, myid, k + 2);
            int s3 = __shfl_sync(0xffffffffu, myid, k + 3);
            float4 v0 = X[(size_t)s0 * 32 + lane];
            float4 v1 = X[(size_t)s1 * 32 + lane];
            float4 v2 = X[(size_t)s2 * 32 + lane];
            float4 v3 = X[(size_t)s3 * 32 + lane];
            acc.x += v0.x + v1.x + v2.x + v3.x;
            acc.y += v0.y + v1.y + v2.y + v3.y;
            acc.z += v0.z + v1.z + v2.z + v3.z;
            acc.w += v0.w + v1.w + v2.w + v3.w;
        }
        for (; k < cnt; k++) {
            int s = __shfl_sync(0xffffffffu, myid, k);
            float4 v = X[(size_t)s * 32 + lane];
            acc.x += v.x; acc.y += v.y; acc.z += v.z; acc.w += v.w;
        }
    }
    float inv = 1.0f / (float)max(end - beg, 1);
    acc.x *= inv; acc.y *= inv; acc.z *= inv; acc.w *= inv;
    reinterpret_cast<float4*>(g_agg)[(size_t)w * 32 + lane] = acc;
}

// ---------------- mma.sync dense layer, TILE_M=64, single A staging ----------------
#define PAD_K 264
#define ROW_B (PAD_K * 2)        // 528 bytes
#define TILE_M 64
#define SM_AH   0
#define SM_AL   33792
#define SM_BH   67584
#define SM_BL   135168
#define SM_BIAS 202752
#define SM_PROJ 203264
#define SM_ZS   205312
#define SMEM_TOT 209408

__device__ __forceinline__ void mma_pass64(uint32_t Abase, uint32_t Bbase,
                                           float c[2][4][4], int wm, int wn, int lane) {
    #pragma unroll 4
    for (int ks = 0; ks < 16; ks++) {
        int k = ks * 16;
        uint32_t a[2][4];
        #pragma unroll
        for (int mi = 0; mi < 2; mi++) {
            uint32_t addr = Abase + (uint32_t)((wm * 32 + mi * 16 + (lane & 15)) * ROW_B
                                             + (k + (lane >> 4) * 8) * 2);
            ldsm_x4(a[mi][0], a[mi][1], a[mi][2], a[mi][3], addr);
        }
        #pragma unroll
        for (int h = 0; h < 2; h++) {
            uint32_t b[4];
            uint32_t addr = Bbase + (uint32_t)((wn * 32 + h * 16 + (lane & 7) + ((lane >> 4) << 3)) * ROW_B
                                             + (k + ((lane >> 3) & 1) * 8) * 2);
            ldsm_x4(b[0], b[1], b[2], b[3], addr);
            #pragma unroll
            for (int mi = 0; mi < 2; mi++) {
                mma16816(c[mi][h * 2 + 0], a[mi], b + 0);
                mma16816(c[mi][h * 2 + 1], a[mi], b + 2);
            }
        }
    }
}

__global__ void __launch_bounds__(256, 1)
dense_mma_kernel(const float* __restrict__ x,
                 const float* __restrict__ W1l,
                 const float* __restrict__ b1,
                 const float* __restrict__ W1r,
                 int n_nodes, int n_tiles) {
    extern __shared__ char smem[];
    uint32_t sb = smem_u32(smem);
    int tid = threadIdx.x;
    int wid = tid >> 5, lane = tid & 31;
    int wm = wid & 1, wn = wid >> 1;

    float* sbias = (float*)(smem + SM_BIAS);
    float4* sproj = (float4*)(smem + SM_PROJ);
    float4* szs = (float4*)(smem + SM_ZS);

    if (tid < 128) {
        sbias[tid] = b1[tid];
        sproj[tid] = make_float4(g_A[tid], g_A[128 + tid], g_B[tid], g_B[128 + tid]);
    }
    for (int r = wid; r < 128; r += 8) {
        float4 w1 = reinterpret_cast<const float4*>(W1l)[r * 32 + lane];
        float4 w2 = reinterpret_cast<const float4*>(W1r)[r * 32 + lane];
        *(uint2*)(smem + SM_BH + r * ROW_B + 8 * lane) = pack_hi(w1);
        *(uint2*)(smem + SM_BL + r * ROW_B + 8 * lane) = pack_lo(w1);
        *(uint2*)(smem + SM_BH + r * ROW_B + 256 + 8 * lane) = pack_hi(w2);
        *(uint2*)(smem + SM_BL + r * ROW_B + 256 + 8 * lane) = pack_lo(w2);
    }
    __syncthreads();

    uint32_t AHb = sb + SM_AH, ALb = sb + SM_AL, BHb = sb + SM_BH, BLb = sb + SM_BL;

    for (int tile = blockIdx.x; tile < n_tiles; tile += gridDim.x) {
        int base = tile * TILE_M;

        for (int n = wid; n < TILE_M; n += 8) {
            int node = base + n;
            float4 va = make_float4(0.f, 0.f, 0.f, 0.f), vx = va;
            if (node < n_nodes) {
                va = reinterpret_cast<const float4*>(g_agg)[(size_t)node * 32 + lane];
                vx = reinterpret_cast<const float4*>(x)[(size_t)node * 32 + lane];
            }
            *(uint2*)(smem + SM_AH + n * ROW_B + 8 * lane) = pack_hi(va);
            *(uint2*)(smem + SM_AL + n * ROW_B + 8 * lane) = pack_lo(va);
            *(uint2*)(smem + SM_AH + n * ROW_B + 256 + 8 * lane) = pack_hi(vx);
            *(uint2*)(smem + SM_AL + n * ROW_B + 256 + 8 * lane) = pack_lo(vx);
        }
        __syncthreads();

        float c[2][4][4];
        #pragma unroll
        for (int i = 0; i < 2; i++)
            #pragma unroll
            for (int j = 0; j < 4; j++)
                #pragma unroll
                for (int v = 0; v < 4; v++) c[i][j][v] = 0.f;

        mma_pass64(AHb, BHb, c, wm, wn, lane);
        mma_pass64(AHb, BLb, c, wm, wn, lane);
        mma_pass64(ALb, BHb, c, wm, wn, lane);

        float zp[4][4];
        #pragma unroll
        for (int r = 0; r < 4; r++)
            #pragma unroll
            for (int v = 0; v < 4; v++) zp[r][v] = 0.f;

        #pragma unroll
        for (int f = 0; f < 4; f++) {
            int ch0 = wn * 32 + f * 8 + (lane & 3) * 2;
            float b0 = sbias[ch0], b1v = sbias[ch0 + 1];
            float4 p0 = sproj[ch0], p1 = sproj[ch0 + 1];
            #pragma unroll
            for (int mi = 0; mi < 2; mi++) {
                float h00 = fmaxf(c[mi][f][0] + b0, 0.f);
                float h01 = fmaxf(c[mi][f][1] + b1v, 0.f);
                float h10 = fmaxf(c[mi][f][2] + b0, 0.f);
                float h11 = fmaxf(c[mi][f][3] + b1v, 0.f);
                int r0 = mi * 2, r1 = mi * 2 + 1;
                zp[r0][0] += h00 * p0.x + h01 * p1.x;
                zp[r0][1] += h00 * p0.y + h01 * p1.y;
                zp[r0][2] += h00 * p0.z + h01 * p1.z;
                zp[r0][3] += h00 * p0.w + h01 * p1.w;
                zp[r1][0] += h10 * p0.x + h11 * p1.x;
                zp[r1][1] += h10 * p0.y + h11 * p1.y;
                zp[r1][2] += h10 * p0.z + h11 * p1.z;
                zp[r1][3] += h10 * p0.w + h11 * p1.w;
            }
        }
        #pragma unroll
        for (int r = 0; r < 4; r++)
            #pragma unroll
            for (int v = 0; v < 4; v++) {
                zp[r][v] += __shfl_xor_sync(0xffffffffu, zp[r][v], 1);
                zp[r][v] += __shfl_xor_sync(0xffffffffu, zp[r][v], 2);
            }
        if ((lane & 3) == 0) {
            #pragma unroll
            for (int r = 0; r < 4; r++) {
                int row = wm * 32 + (r >> 1) * 16 + (r & 1) * 8 + (lane >> 2);
                szs[wn * TILE_M + row] = make_float4(zp[r][0], zp[r][1], zp[r][2], zp[r][3]);
            }
        }
        __syncthreads();

        if (tid < TILE_M) {
            float4 t0 = szs[tid], t1 = szs[TILE_M + tid];
            float4 t2 = szs[2 * TILE_M + tid], t3 = szs[3 * TILE_M + tid];
            int node = base + tid;
            if (node < n_nodes) {
                *(float2*)&g_z[node * 2] = make_float2(t0.x + t1.x + t2.x + t3.x,
                                                       t0.y + t1.y + t2.y + t3.y);
                *(float2*)&g_s[node * 2] = make_float2(t0.z + t1.z + t2.z + t3.z,
                                                       t0.w + t1.w + t2.w + t3.w);
            }
        }
        __syncthreads();
    }
}

// ---------------- gather2 (half-warp per node) + zero counts for next run ----------------
__global__ void gather2_kernel(float* __restrict__ out, int n_nodes) {
    int gtid = blockIdx.x * blockDim.x + threadIdx.x;
    int stride = gridDim.x * blockDim.x;
    for (int i = gtid; i < n_nodes; i += stride) g_count[i] = 0;

    int w = gtid >> 4;
    int l = threadIdx.x & 15;
    if (w >= n_nodes) return;
    int beg = g_rowptr[w];
    int end = g_rowptr[w + 1];
    float acc0 = 0.f, acc1 = 0.f;
    for (int j = beg + l; j < end; j += 16) {
        int s = g_srcs[j];
        float2 zv = reinterpret_cast<const float2*>(g_z)[s];
        acc0 += zv.x;
        acc1 += zv.y;
    }
    #pragma unroll
    for (int off = 8; off > 0; off >>= 1) {
        acc0 += __shfl_xor_sync(0xffffffffu, acc0, off);
        acc1 += __shfl_xor_sync(0xffffffffu, acc1, off);
    }
    if (l == 0) {
        float inv = 1.0f / (float)max(end - beg, 1);
        out[w * 2 + 0] = acc0 * inv + g_s[w * 2 + 0] + g_c[0];
        out[w * 2 + 1] = acc1 * inv + g_s[w * 2 + 1] + g_c[1];
    }
}

extern "C" void kernel_launch(void* const* d_in, const int* in_sizes, int n_in,
                              void* d_out, int out_size) {
    const float* x        = (const float*)d_in[0];
    const void*  ei       = d_in[1];
    const float* W1l      = (const float*)d_in[2];
    const float* b1       = (const float*)d_in[3];
    const float* W1r      = (const float*)d_in[4];
    const float* W2l      = (const float*)d_in[5];
    const float* b2       = (const float*)d_in[6];
    const float* W2r      = (const float*)d_in[7];
    const float* Wlin     = (const float*)d_in[8];
    const float* blin     = (const float*)d_in[9];
    float* out            = (float*)d_out;

    int n = in_sizes[0] / FEAT;
    int E = in_sizes[1] / 2;
    int n_tiles = (n + TILE_M - 1) / TILE_M;
    int nb = (n + SCAN_BLK - 1) / SCAN_BLK;

    cudaFuncSetAttribute(dense_mma_kernel, cudaFuncAttributeMaxDynamicSharedMemorySize, SMEM_TOT);

    count_kernel<<<(E + 2047) / 2048, 256>>>(ei, E, W2l, b2, W2r, Wlin, blin);
    scanA_kernel<<<nb, SCAN_BLK>>>(n);
    scanC_kernel<<<nb, SCAN_BLK>>>(n, E);
    fill_kernel<<<(E + 2047) / 2048, 256>>>(ei, E);
    gather1_kernel<<<(n * 32 + 255) / 256, 256>>>(x, n);
    dense_mma_kernel<<<152, 256, SMEM_TOT>>>(x, W1l, b1, W1r, n, n_tiles);
    gather2_kernel<<<(n * 16 + 255) / 256, 256>>>(out, n);
}

// round 14
// speedup vs baseline: 1.0152x; 1.0152x over previous
#include <cuda_runtime.h>
#include <cuda_bf16.h>
#include <cstdint>

#define NN 100000
#define EE 1600000
#define FEAT 128
#define SCAN_BLK 1024

// ---------------- device scratch ----------------
__device__ float g_agg[NN * FEAT];
__device__ float g_z[NN * 2];
__device__ float g_s[NN * 2];
__device__ float g_A[2 * FEAT];
__device__ float g_B[2 * FEAT];
__device__ float g_c[2];
__device__ int g_count[NN];      // zero at load; re-zeroed by gather2 tail each run
__device__ int g_rowptr[NN + 1];
__device__ int g_rank[EE];       // per-edge rank within its dst list (from count_kernel)
__device__ int g_bsum[128];
__device__ int g_srcs[EE];

// ---------------- helpers ----------------
__device__ __forceinline__ uint32_t smem_u32(const void* p) {
    uint32_t a;
    asm("{ .reg .u64 t; cvta.to.shared.u64 t, %1; cvt.u32.u64 %0, t; }" : "=r"(a) : "l"(p));
    return a;
}
__device__ __forceinline__ void ldsm_x4(uint32_t& r0, uint32_t& r1, uint32_t& r2, uint32_t& r3,
                                        uint32_t addr) {
    asm volatile("ldmatrix.sync.aligned.m8n8.x4.shared.b16 {%0,%1,%2,%3}, [%4];"
                 : "=r"(r0), "=r"(r1), "=r"(r2), "=r"(r3) : "r"(addr));
}
__device__ __forceinline__ void mma16816(float* c, const uint32_t* a, const uint32_t* b) {
    asm volatile(
        "mma.sync.aligned.m16n8k16.row.col.f32.bf16.bf16.f32 "
        "{%0,%1,%2,%3}, {%4,%5,%6,%7}, {%8,%9}, {%0,%1,%2,%3};"
        : "+f"(c[0]), "+f"(c[1]), "+f"(c[2]), "+f"(c[3])
        : "r"(a[0]), "r"(a[1]), "r"(a[2]), "r"(a[3]), "r"(b[0]), "r"(b[1]));
}
__device__ __forceinline__ uint2 pack_hi(float4 v) {
    __nv_bfloat162 p01 = __floats2bfloat162_rn(v.x, v.y);
    __nv_bfloat162 p23 = __floats2bfloat162_rn(v.z, v.w);
    return make_uint2(*(uint32_t*)&p01, *(uint32_t*)&p23);
}
__device__ __forceinline__ uint2 pack_lo(float4 v) {
    __nv_bfloat162 p01 = __floats2bfloat162_rn(v.x, v.y);
    __nv_bfloat162 p23 = __floats2bfloat162_rn(v.z, v.w);
    float4 lo;
    lo.x = v.x - __bfloat162float(__low2bfloat16(p01));
    lo.y = v.y - __bfloat162float(__high2bfloat16(p01));
    lo.z = v.z - __bfloat162float(__low2bfloat16(p23));
    lo.w = v.w - __bfloat162float(__high2bfloat16(p23));
    __nv_bfloat162 q01 = __floats2bfloat162_rn(lo.x, lo.y);
    __nv_bfloat162 q23 = __floats2bfloat162_rn(lo.z, lo.w);
    return make_uint2(*(uint32_t*)&q01, *(uint32_t*)&q23);
}
__device__ __forceinline__ int probe_is64(const void* ei) {
    const int* p = (const int*)ei;
    int orr = 0;
    #pragma unroll
    for (int j = 1; j < 32; j += 2) orr |= p[j];
    return (orr == 0) ? 1 : 0;
}
__device__ __forceinline__ int edge_at(const void* ei, int is64, long long idx) {
    if (is64) return (int)((const long long*)ei)[idx];
    return ((const int*)ei)[idx];
}

// ---------------- count (+rank capture) + weight folding in block 0 ----------------
__global__ void count_kernel(const void* __restrict__ ei, int E,
                             const float* __restrict__ W2l, const float* __restrict__ b2,
                             const float* __restrict__ W2r, const float* __restrict__ Wlin,
                             const float* __restrict__ blin) {
    if (blockIdx.x == 0) {
        int t = threadIdx.x;
        if (t < 256) {
            int o = t >> 7, f = t & 127;
            float a = 0.f, b = 0.f;
            #pragma unroll
            for (int k = 0; k < 4; k++) {
                float w = Wlin[o * 4 + k];
                a += w * W2l[k * FEAT + f];
                b += w * W2r[k * FEAT + f];
            }
            g_A[o * FEAT + f] = a;
            g_B[o * FEAT + f] = b;
        }
        if (t < 2) {
            float c = blin[t];
            #pragma unroll
            for (int k = 0; k < 4; k++) c += Wlin[t * 4 + k] * b2[k];
            g_c[t] = c;
        }
    }
    int is64 = probe_is64(ei);
    int e0 = blockIdx.x * (blockDim.x * 8) + threadIdx.x;
    int d[8];
    #pragma unroll
    for (int u = 0; u < 8; u++) {
        int e = e0 + u * blockDim.x;
        d[u] = (e < E) ? edge_at(ei, is64, (long long)E + e) : -1;
    }
    #pragma unroll
    for (int u = 0; u < 8; u++)
        if (d[u] >= 0) {
            int r = atomicAdd(&g_count[d[u]], 1);
            g_rank[e0 + u * blockDim.x] = r;
        }
}

// ---------------- scanA: warp-shuffle block scan ----------------
__global__ void scanA_kernel(int n) {
    __shared__ int wsum[32];
    int t = threadIdx.x;
    int lane = t & 31, wd = t >> 5;
    int idx = blockIdx.x * SCAN_BLK + t;
    int v0 = (idx < n) ? g_count[idx] : 0;
    int v = v0;
    #pragma unroll
    for (int off = 1; off < 32; off <<= 1) {
        int u = __shfl_up_sync(0xffffffffu, v, off);
        if (lane >= off) v += u;
    }
    if (lane == 31) wsum[wd] = v;
    __syncthreads();
    if (wd == 0) {
        int w0 = wsum[lane];
        int wv = w0;
        #pragma unroll
        for (int off = 1; off < 32; off <<= 1) {
            int u = __shfl_up_sync(0xffffffffu, wv, off);
            if (lane >= off) wv += u;
        }
        wsum[lane] = wv - w0;          // exclusive warp offset
        if (lane == 31) g_bsum[blockIdx.x] = wv;   // block total
    }
    __syncthreads();
    if (idx <= n) g_rowptr[idx] = v + wsum[wd] - v0;   // exclusive prefix
}

// ---------------- scanC: add cross-block offsets (block-local reduction) ----------------
__global__ void scanC_kernel(int n, int E) {
    __shared__ int sb[128];
    int t = threadIdx.x;
    int bid = blockIdx.x;
    if (t < 128) sb[t] = (t < bid) ? g_bsum[t] : 0;
    __syncthreads();
    #pragma unroll
    for (int off = 64; off > 0; off >>= 1) {
        if (t < off) sb[t] += sb[t + off];
        __syncthreads();
    }
    int boff = sb[0];
    int idx = bid * SCAN_BLK + t;
    if (idx < n) g_rowptr[idx] += boff;
    if (idx == 0) g_rowptr[n] = E;
}

// ---------------- fill: atomic-free via precomputed ranks ----------------
__global__ void fill_kernel(const void* __restrict__ ei, int E) {
    int is64 = probe_is64(ei);
    int e0 = blockIdx.x * (blockDim.x * 8) + threadIdx.x;
    int s[8], slot[8];
    #pragma unroll
    for (int u = 0; u < 8; u++) {
        int e = e0 + u * blockDim.x;
        if (e < E) {
            s[u] = edge_at(ei, is64, e);
            int d = edge_at(ei, is64, (long long)E + e);
            slot[u] = g_rowptr[d] + g_rank[e];
        } else slot[u] = -1;
    }
    #pragma unroll
    for (int u = 0; u < 8; u++)
        if (slot[u] >= 0) g_srcs[slot[u]] = s[u];
}

// ---------------- gather1 (warp per node) ----------------
__global__ void gather1_kernel(const float* __restrict__ x, int n_nodes) {
    int w = (blockIdx.x * blockDim.x + threadIdx.x) >> 5;
    int lane = threadIdx.x & 31;
    if (w >= n_nodes) return;
    int beg = g_rowptr[w];
    int end = g_rowptr[w + 1];
    float4 acc = make_float4(0.f, 0.f, 0.f, 0.f);
    const float4* X = reinterpret_cast<const float4*>(x);
    for (int j0 = beg; j0 < end; j0 += 32) {
        int myid = (j0 + lane < end) ? g_srcs[j0 + lane] : 0;
        int cnt = min(32, end - j0);
        int k = 0;
        for (; k + 4 <= cnt; k += 4) {
            int s0 = __shfl_sync(0xffffffffu, myid, k);
            int s1 = __shfl_sync(0xffffffffu, myid, k + 1);
            int s2 = __shfl_sync(0xffffffffu, myid, k + 2);
            int s3 = __shfl_sync(0xffffffffu, myid, k + 3);
            float4 v0 = X[(size_t)s0 * 32 + lane];
            float4 v1 = X[(size_t)s1 * 32 + lane];
            float4 v2 = X[(size_t)s2 * 32 + lane];
            float4 v3 = X[(size_t)s3 * 32 + lane];
            acc.x += v0.x + v1.x + v2.x + v3.x;
            acc.y += v0.y + v1.y + v2.y + v3.y;
            acc.z += v0.z + v1.z + v2.z + v3.z;
            acc.w += v0.w + v1.w + v2.w + v3.w;
        }
        for (; k < cnt; k++) {
            int s = __shfl_sync(0xffffffffu, myid, k);
            float4 v = X[(size_t)s * 32 + lane];
            acc.x += v.x; acc.y += v.y; acc.z += v.z; acc.w += v.w;
        }
    }
    float inv = 1.0f / (float)max(end - beg, 1);
    acc.x *= inv; acc.y *= inv; acc.z *= inv; acc.w *= inv;
    reinterpret_cast<float4*>(g_agg)[(size_t)w * 32 + lane] = acc;
}

// ---------------- mma.sync dense layer, TILE_M=64, single A staging ----------------
#define PAD_K 264
#define ROW_B (PAD_K * 2)        // 528 bytes
#define TILE_M 64
#define SM_AH   0
#define SM_AL   33792
#define SM_BH   67584
#define SM_BL   135168
#define SM_BIAS 202752
#define SM_PROJ 203264
#define SM_ZS   205312
#define SMEM_TOT 209408

__device__ __forceinline__ void mma_pass64(uint32_t Abase, uint32_t Bbase,
                                           float c[2][4][4], int wm, int wn, int lane) {
    #pragma unroll 4
    for (int ks = 0; ks < 16; ks++) {
        int k = ks * 16;
        uint32_t a[2][4];
        #pragma unroll
        for (int mi = 0; mi < 2; mi++) {
            uint32_t addr = Abase + (uint32_t)((wm * 32 + mi * 16 + (lane & 15)) * ROW_B
                                             + (k + (lane >> 4) * 8) * 2);
            ldsm_x4(a[mi][0], a[mi][1], a[mi][2], a[mi][3], addr);
        }
        #pragma unroll
        for (int h = 0; h < 2; h++) {
            uint32_t b[4];
            uint32_t addr = Bbase + (uint32_t)((wn * 32 + h * 16 + (lane & 7) + ((lane >> 4) << 3)) * ROW_B
                                             + (k + ((lane >> 3) & 1) * 8) * 2);
            ldsm_x4(b[0], b[1], b[2], b[3], addr);
            #pragma unroll
            for (int mi = 0; mi < 2; mi++) {
                mma16816(c[mi][h * 2 + 0], a[mi], b + 0);
                mma16816(c[mi][h * 2 + 1], a[mi], b + 2);
            }
        }
    }
}

__global__ void __launch_bounds__(256, 1)
dense_mma_kernel(const float* __restrict__ x,
                 const float* __restrict__ W1l,
                 const float* __restrict__ b1,
                 const float* __restrict__ W1r,
                 int n_nodes, int n_tiles) {
    extern __shared__ char smem[];
    uint32_t sb = smem_u32(smem);
    int tid = threadIdx.x;
    int wid = tid >> 5, lane = tid & 31;
    int wm = wid & 1, wn = wid >> 1;

    float* sbias = (float*)(smem + SM_BIAS);
    float4* sproj = (float4*)(smem + SM_PROJ);
    float4* szs = (float4*)(smem + SM_ZS);

    if (tid < 128) {
        sbias[tid] = b1[tid];
        sproj[tid] = make_float4(g_A[tid], g_A[128 + tid], g_B[tid], g_B[128 + tid]);
    }
    for (int r = wid; r < 128; r += 8) {
        float4 w1 = reinterpret_cast<const float4*>(W1l)[r * 32 + lane];
        float4 w2 = reinterpret_cast<const float4*>(W1r)[r * 32 + lane];
        *(uint2*)(smem + SM_BH + r * ROW_B + 8 * lane) = pack_hi(w1);
        *(uint2*)(smem + SM_BL + r * ROW_B + 8 * lane) = pack_lo(w1);
        *(uint2*)(smem + SM_BH + r * ROW_B + 256 + 8 * lane) = pack_hi(w2);
        *(uint2*)(smem + SM_BL + r * ROW_B + 256 + 8 * lane) = pack_lo(w2);
    }
    __syncthreads();

    uint32_t AHb = sb + SM_AH, ALb = sb + SM_AL, BHb = sb + SM_BH, BLb = sb + SM_BL;

    for (int tile = blockIdx.x; tile < n_tiles; tile += gridDim.x) {
        int base = tile * TILE_M;

        for (int n = wid; n < TILE_M; n += 8) {
            int node = base + n;
            float4 va = make_float4(0.f, 0.f, 0.f, 0.f), vx = va;
            if (node < n_nodes) {
                va = reinterpret_cast<const float4*>(g_agg)[(size_t)node * 32 + lane];
                vx = reinterpret_cast<const float4*>(x)[(size_t)node * 32 + lane];
            }
            *(uint2*)(smem + SM_AH + n * ROW_B + 8 * lane) = pack_hi(va);
            *(uint2*)(smem + SM_AL + n * ROW_B + 8 * lane) = pack_lo(va);
            *(uint2*)(smem + SM_AH + n * ROW_B + 256 + 8 * lane) = pack_hi(vx);
            *(uint2*)(smem + SM_AL + n * ROW_B + 256 + 8 * lane) = pack_lo(vx);
        }
        __syncthreads();

        float c[2][4][4];
        #pragma unroll
        for (int i = 0; i < 2; i++)
            #pragma unroll
            for (int j = 0; j < 4; j++)
                #pragma unroll
                for (int v = 0; v < 4; v++) c[i][j][v] = 0.f;

        mma_pass64(AHb, BHb, c, wm, wn, lane);
        mma_pass64(AHb, BLb, c, wm, wn, lane);
        mma_pass64(ALb, BHb, c, wm, wn, lane);

        float zp[4][4];
        #pragma unroll
        for (int r = 0; r < 4; r++)
            #pragma unroll
            for (int v = 0; v < 4; v++) zp[r][v] = 0.f;

        #pragma unroll
        for (int f = 0; f < 4; f++) {
            int ch0 = wn * 32 + f * 8 + (lane & 3) * 2;
            float b0 = sbias[ch0], b1v = sbias[ch0 + 1];
            float4 p0 = sproj[ch0], p1 = sproj[ch0 + 1];
            #pragma unroll
            for (int mi = 0; mi < 2; mi++) {
                float h00 = fmaxf(c[mi][f][0] + b0, 0.f);
                float h01 = fmaxf(c[mi][f][1] + b1v, 0.f);
                float h10 = fmaxf(c[mi][f][2] + b0, 0.f);
                float h11 = fmaxf(c[mi][f][3] + b1v, 0.f);
                int r0 = mi * 2, r1 = mi * 2 + 1;
                zp[r0][0] += h00 * p0.x + h01 * p1.x;
                zp[r0][1] += h00 * p0.y + h01 * p1.y;
                zp[r0][2] += h00 * p0.z + h01 * p1.z;
                zp[r0][3] += h00 * p0.w + h01 * p1.w;
                zp[r1][0] += h10 * p0.x + h11 * p1.x;
                zp[r1][1] += h10 * p0.y + h11 * p1.y;
                zp[r1][2] += h10 * p0.z + h11 * p1.z;
                zp[r1][3] += h10 * p0.w + h11 * p1.w;
            }
        }
        #pragma unroll
        for (int r = 0; r < 4; r++)
            #pragma unroll
            for (int v = 0; v < 4; v++) {
                zp[r][v] += __shfl_xor_sync(0xffffffffu, zp[r][v], 1);
                zp[r][v] += __shfl_xor_sync(0xffffffffu, zp[r][v], 2);
            }
        if ((lane & 3) == 0) {
            #pragma unroll
            for (int r = 0; r < 4; r++) {
                int row = wm * 32 + (r >> 1) * 16 + (r & 1) * 8 + (lane >> 2);
                szs[wn * TILE_M + row] = make_float4(zp[r][0], zp[r][1], zp[r][2], zp[r][3]);
            }
        }
        __syncthreads();

        if (tid < TILE_M) {
            float4 t0 = szs[tid], t1 = szs[TILE_M + tid];
            float4 t2 = szs[2 * TILE_M + tid], t3 = szs[3 * TILE_M + tid];
            int node = base + tid;
            if (node < n_nodes) {
                *(float2*)&g_z[node * 2] = make_float2(t0.x + t1.x + t2.x + t3.x,
                                                       t0.y + t1.y + t2.y + t3.y);
                *(float2*)&g_s[node * 2] = make_float2(t0.z + t1.z + t2.z + t3.z,
                                                       t0.w + t1.w + t2.w + t3.w);
            }
        }
        __syncthreads();
    }
}

// ---------------- gather2 (half-warp per node) + zero counts for next run ----------------
__global__ void gather2_kernel(float* __restrict__ out, int n_nodes) {
    int gtid = blockIdx.x * blockDim.x + threadIdx.x;
    int stride = gridDim.x * blockDim.x;
    for (int i = gtid; i < n_nodes; i += stride) g_count[i] = 0;

    int w = gtid >> 4;
    int l = threadIdx.x & 15;
    if (w >= n_nodes) return;
    int beg = g_rowptr[w];
    int end = g_rowptr[w + 1];
    float acc0 = 0.f, acc1 = 0.f;
    for (int j = beg + l; j < end; j += 16) {
        int s = g_srcs[j];
        float2 zv = reinterpret_cast<const float2*>(g_z)[s];
        acc0 += zv.x;
        acc1 += zv.y;
    }
    #pragma unroll
    for (int off = 8; off > 0; off >>= 1) {
        acc0 += __shfl_xor_sync(0xffffffffu, acc0, off);
        acc1 += __shfl_xor_sync(0xffffffffu, acc1, off);
    }
    if (l == 0) {
        float inv = 1.0f / (float)max(end - beg, 1);
        out[w * 2 + 0] = acc0 * inv + g_s[w * 2 + 0] + g_c[0];
        out[w * 2 + 1] = acc1 * inv + g_s[w * 2 + 1] + g_c[1];
    }
}

extern "C" void kernel_launch(void* const* d_in, const int* in_sizes, int n_in,
                              void* d_out, int out_size) {
    const float* x        = (const float*)d_in[0];
    const void*  ei       = d_in[1];
    const float* W1l      = (const float*)d_in[2];
    const float* b1       = (const float*)d_in[3];
    const float* W1r      = (const float*)d_in[4];
    const float* W2l      = (const float*)d_in[5];
    const float* b2       = (const float*)d_in[6];
    const float* W2r      = (const float*)d_in[7];
    const float* Wlin     = (const float*)d_in[8];
    const float* blin     = (const float*)d_in[9];
    float* out            = (float*)d_out;

    int n = in_sizes[0] / FEAT;
    int E = in_sizes[1] / 2;
    int n_tiles = (n + TILE_M - 1) / TILE_M;
    int nb = (n + SCAN_BLK - 1) / SCAN_BLK;

    cudaFuncSetAttribute(dense_mma_kernel, cudaFuncAttributeMaxDynamicSharedMemorySize, SMEM_TOT);

    count_kernel<<<(E + 2047) / 2048, 256>>>(ei, E, W2l, b2, W2r, Wlin, blin);
    scanA_kernel<<<nb, SCAN_BLK>>>(n);
    scanC_kernel<<<nb, SCAN_BLK>>>(n, E);
    fill_kernel<<<(E + 2047) / 2048, 256>>>(ei, E);
    gather1_kernel<<<(n * 32 + 255) / 256, 256>>>(x, n);
    dense_mma_kernel<<<152, 256, SMEM_TOT>>>(x, W1l, b1, W1r, n, n_tiles);
    gather2_kernel<<<(n * 16 + 255) / 256, 256>>>(out, n);
}